// round 8
// baseline (speedup 1.0000x reference)
#include <cuda_runtime.h>
#include <cuda_fp16.h>
#include <math.h>
#include <stdint.h>

#define TT 512
#define BB 64
#define HH 1024
#define G4 4096
#define NCTA 128
#define WL 4          // gx lead window
#define RSLOTS 5      // smem ring slots (WL+1)

// ---------------- device scratch (static, no runtime alloc) ----------------
// Wh per-CTA A-frag blob: [c128][mt2][kt64][lane32][reg4] fp16
static __device__ uint32_t g_whp[(size_t)NCTA * 16384];
// Wx per-CTA A-frag blob: same layout
static __device__ uint32_t g_wxp[(size_t)NCTA * 16384];
// X B-frag blob: [t512][kt64][nt8][lane32][reg2] fp16  (64 MB)
static __device__ uint32_t g_xb[(size_t)TT * 32768];
// h B-frag (double buffered): [buf2][kt64][nt8][lane32][reg2]
static __device__ uint32_t g_hfrag[2][32768];
static __device__ int g_arrive;

// ---------------- mma.sync m16n8k16 fp16 (base sm_80+) ----------------
__device__ __forceinline__ void mma16816(float* c, const uint32_t* a, const uint32_t* b) {
    asm volatile(
        "mma.sync.aligned.m16n8k16.row.col.f32.f16.f16.f32 "
        "{%0,%1,%2,%3}, {%4,%5,%6,%7}, {%8,%9}, {%0,%1,%2,%3};"
        : "+f"(c[0]), "+f"(c[1]), "+f"(c[2]), "+f"(c[3])
        : "r"(a[0]), "r"(a[1]), "r"(a[2]), "r"(a[3]), "r"(b[0]), "r"(b[1]));
}

__device__ __forceinline__ void bar_arrive(int* p) {
    asm volatile("red.release.gpu.global.add.s32 [%0], 1;" :: "l"(p) : "memory");
}
__device__ __forceinline__ int bar_poll(const int* p) {
    int v;
    asm volatile("ld.acquire.gpu.global.s32 %0, [%1];" : "=r"(v) : "l"(p) : "memory");
    return v;
}

// ---------------------------------------------------------------------------
// Pack kernels. Fragment layouts (validated R3-R6):
// A (16x16): lane=((r&7)<<2)|((kk>>1)&3), reg=((kk>>3)<<1)|(r>>3), half=kk&1
// B (8x16):  lane=((n&7)<<2)|((kk>>1)&3), reg=kk>>3,               half=kk&1
// NOTE: destination selected DEVICE-SIDE (host code must not take the address
// of a __device__ global — that was the R7 bug).
// ---------------------------------------------------------------------------
__global__ __launch_bounds__(256) void pack_wp(const float* __restrict__ Wsrc,
                                               int which) {
    uint32_t* dst = which ? g_wxp : g_whp;
    int idx = blockIdx.x * 256 + threadIdx.x;   // 4096*1024
    int row = idx >> 10, k = idx & 1023;
    int g = row >> 10, u = row & 1023;
    int c = u >> 3, ul = u & 7;
    int rm = g * 8 + ul;                        // row within CTA's 32
    int mt = rm >> 4, r = rm & 15;
    int kt = k >> 4, kk = k & 15;
    int lane = ((r & 7) << 2) | ((kk >> 1) & 3);
    int reg = ((kk >> 3) << 1) | (r >> 3);
    int half = kk & 1;
    size_t base = (size_t)c * 16384 + ((size_t)mt * 64 + kt) * 128 + lane * 4 + reg;
    ((__half*)&dst[base])[half] = __float2half_rn(Wsrc[idx]);
}

__global__ __launch_bounds__(256) void pack_xb(const float* __restrict__ X) {
    size_t idx = (size_t)blockIdx.x * 256 + threadIdx.x;  // 512*64*1024
    int t = (int)(idx >> 16);
    int b = (int)(idx >> 10) & 63;
    int k = (int)(idx & 1023);
    int kt = k >> 4, kk = k & 15;
    int nt = b >> 3;
    int lane = ((b & 7) << 2) | ((kk >> 1) & 3);
    int reg = kk >> 3;
    int half = kk & 1;
    size_t wi = (size_t)t * 32768 + ((size_t)(kt * 8 + nt) * 32 + lane) * 2 + reg;
    ((__half*)&g_xb[wi])[half] = __float2half_rn(X[idx]);
}

__global__ __launch_bounds__(256) void pack_h0(const float* __restrict__ h0) {
    int idx = blockIdx.x * 256 + threadIdx.x;   // 64*1024
    int b = idx >> 10, u = idx & 1023;
    int kt = u >> 4, kk = u & 15;
    int nt = b >> 3;
    int lane = ((b & 7) << 2) | ((kk >> 1) & 3);
    int reg = kk >> 3;
    int half = kk & 1;
    size_t wi = ((size_t)(kt * 8 + nt) * 32 + lane) * 2 + reg;
    ((__half*)&g_hfrag[0][wi])[half] = __float2half_rn(h0[idx]);
}

__global__ void reset_bar() { g_arrive = 0; }

// ---------------------------------------------------------------------------
// Fused persistent kernel: 128 CTAs x 256 threads.
// CTA c owns cells [c*8, c*8+8) (32 gate rows). Warp w owns nt = w (8 batch cols),
// full M (2 mtiles) and full K — B fragments read once, no K-reduction.
// Per step: rec GEMM (h[t]) + gx GEMM for t+WL into smem ring + cell update.
// ---------------------------------------------------------------------------
#define SO_WX   65536
#define SO_RING 131072
#define SO_GS   (SO_RING + RSLOTS * 32 * 66 * 4)    // 173312
#define SO_CS   (SO_GS + 32 * 66 * 4)               // 181760
#define SO_BS   (SO_CS + 2048)                      // 183808
#define SM_TOTAL (SO_BS + 128)                      // 183936

__global__ __launch_bounds__(256, 1) void lstm_persist(
    const float* __restrict__ c0,
    const float* __restrict__ bx, const float* __restrict__ bh,
    float* __restrict__ out,
    float* __restrict__ hfin, float* __restrict__ cfin,
    int full)
{
    extern __shared__ __align__(16) char sm[];
    uint32_t (*whs)[64][128] = (uint32_t (*)[64][128])sm;            // [mt][kt][lane*4+reg]
    uint32_t (*wxs)[64][128] = (uint32_t (*)[64][128])(sm + SO_WX);
    float (*ring)[32][66] = (float (*)[32][66])(sm + SO_RING);
    float (*Gs)[66] = (float (*)[66])(sm + SO_GS);
    float* cs = (float*)(sm + SO_CS);
    float* bsum = (float*)(sm + SO_BS);

    const int cta = blockIdx.x;
    const int tid = threadIdx.x;
    const int w = tid >> 5, lane = tid & 31;     // warp w = nt

    // ---- init: Wh + Wx slices into smem, cell state, bias sums ----
    {
        const uint4* s1 = (const uint4*)(g_whp + (size_t)cta * 16384);
        const uint4* s2 = (const uint4*)(g_wxp + (size_t)cta * 16384);
        uint4* d1 = (uint4*)sm;
        uint4* d2 = (uint4*)(sm + SO_WX);
        for (int i = tid; i < 4096; i += 256) { d1[i] = s1[i]; d2[i] = s2[i]; }
        for (int i = tid; i < 512; i += 256) {
            int b = i >> 3, ul = i & 7;
            cs[i] = c0[(size_t)b * HH + cta * 8 + ul];
        }
        if (tid < 32) {
            int g = tid >> 3, u = cta * 8 + (tid & 7);
            int col = g * HH + u;
            bsum[tid] = bx[col] + bh[col];
        }
    }
    __syncthreads();

    const int c0q = (lane & 3) * 2;    // fragment col offset
    const int r0q = lane >> 2;         // fragment row offset

    // ---- gx slice for timestep tw -> ring[slot] (each warp: nt = w) ----
    auto gx_slice = [&](int tw, int slot) {
        float ga[2][4];
#pragma unroll
        for (int i = 0; i < 2; i++)
#pragma unroll
            for (int j = 0; j < 4; j++) ga[i][j] = 0.f;
        const uint32_t* Bx = g_xb + (size_t)tw * 32768;
#pragma unroll 4
        for (int kt = 0; kt < 64; kt++) {
            uint2 bf = __ldcg((const uint2*)(Bx + (uint32_t)(kt * 8 + w) * 64 + lane * 2));
            uint4 a0 = *(const uint4*)&wxs[0][kt][lane * 4];
            uint4 a1 = *(const uint4*)&wxs[1][kt][lane * 4];
            mma16816(ga[0], (const uint32_t*)&a0, (const uint32_t*)&bf);
            mma16816(ga[1], (const uint32_t*)&a1, (const uint32_t*)&bf);
        }
        const int col = w * 8 + c0q;
#pragma unroll
        for (int mt = 0; mt < 2; mt++) {
            int ra = mt * 16 + r0q;
            ring[slot][ra][col]     = ga[mt][0] + bsum[ra];
            ring[slot][ra][col + 1] = ga[mt][1] + bsum[ra];
            ring[slot][ra + 8][col]     = ga[mt][2] + bsum[ra + 8];
            ring[slot][ra + 8][col + 1] = ga[mt][3] + bsum[ra + 8];
        }
    };

    // lead-in: gx for t = 0..WL-1 into slots 0..WL-1
    for (int tw = 0; tw < WL; tw++) gx_slice(tw, tw);

    for (int t = 0; t < TT; t++) {
        // ---- rec GEMM: D[32,64] = Wh_slice @ h[t] ----
        float acc[2][4];
#pragma unroll
        for (int i = 0; i < 2; i++)
#pragma unroll
            for (int j = 0; j < 4; j++) acc[i][j] = 0.f;
        const uint32_t* Bf = &g_hfrag[t & 1][0];
#pragma unroll 4
        for (int kt = 0; kt < 64; kt++) {
            uint2 bf = __ldcg((const uint2*)(Bf + (uint32_t)(kt * 8 + w) * 64 + lane * 2));
            uint4 a0 = *(const uint4*)&whs[0][kt][lane * 4];
            uint4 a1 = *(const uint4*)&whs[1][kt][lane * 4];
            mma16816(acc[0], (const uint32_t*)&a0, (const uint32_t*)&bf);
            mma16816(acc[1], (const uint32_t*)&a1, (const uint32_t*)&bf);
        }

        // ---- gx GEMM for t+WL (fills tensor pipe; X is constant, no ordering) ----
        if (t + WL < TT) gx_slice(t + WL, (t + WL) % RSLOTS);

        // ---- scatter rec acc -> Gs ----
        {
            const int col = w * 8 + c0q;
#pragma unroll
            for (int mt = 0; mt < 2; mt++) {
                int ra = mt * 16 + r0q;
                Gs[ra][col]     = acc[mt][0];
                Gs[ra][col + 1] = acc[mt][1];
                Gs[ra + 8][col]     = acc[mt][2];
                Gs[ra + 8][col + 1] = acc[mt][3];
            }
        }
        __syncthreads();

        // ---- cell update: 2 cells per thread ----
        const int slot = t % RSLOTS;
        float* outt = out + (size_t)t * BB * HH;
        const int nb = (t + 1) & 1;
        float hsave[2];
#pragma unroll
        for (int pp = 0; pp < 2; pp++) {
            const int p = tid + pp * 256;
            const int b = p >> 3, ul = p & 7;
            const int u = cta * 8 + ul;

            float x0 = Gs[ul][b]      + ring[slot][ul][b];
            float x1 = Gs[8 + ul][b]  + ring[slot][8 + ul][b];
            float x2 = Gs[16 + ul][b] + ring[slot][16 + ul][b];
            float x3 = Gs[24 + ul][b] + ring[slot][24 + ul][b];

            float ig = 1.f / (1.f + __expf(-x0));
            float fg = 1.f / (1.f + __expf(-x1));
            float og = 1.f / (1.f + __expf(-x2));
            float ng = tanhf(x3);

            float cprev = cs[p];
            float cnew = fg * cprev + ig * ng;
            float hnew = og * tanhf(cnew);
            cs[p] = cnew;
            hsave[pp] = hnew;

            // publish next-step B fragment (fp16)
            int kt = u >> 4, kk = u & 15, nt = b >> 3;
            int lt = ((b & 7) << 2) | ((kk >> 1) & 3);
            int rg = kk >> 3, hf = kk & 1;
            size_t wi = ((size_t)(kt * 8 + nt) * 32 + lt) * 2 + rg;
            ((__half*)&g_hfrag[nb][wi])[hf] = __float2half_rn(hnew);

            if (t == TT - 1 && full) {
                hfin[(size_t)b * HH + u] = hnew;
                cfin[(size_t)b * HH + u] = cnew;
            }
        }
        __syncthreads();   // Gs/ring slot reuse + all h stores done before release

        if (tid == 0) bar_arrive(&g_arrive);

        // off-critical-path output stores
#pragma unroll
        for (int pp = 0; pp < 2; pp++) {
            const int p = tid + pp * 256;
            const int b = p >> 3, ul = p & 7;
            outt[(size_t)b * HH + cta * 8 + ul] = hsave[pp];
        }

        if (tid == 0) {
            const int target = NCTA * (t + 1);
            while (bar_poll(&g_arrive) < target) { }
        }
        __syncthreads();
    }
}

// ---------------------------------------------------------------------------
extern "C" void kernel_launch(void* const* d_in, const int* in_sizes, int n_in,
                              void* d_out, int out_size)
{
    const float* input_ = (const float*)d_in[0];
    const float* h0     = (const float*)d_in[1];
    const float* c0     = (const float*)d_in[2];
    const float* Wx     = (const float*)d_in[3];
    const float* Wh     = (const float*)d_in[4];
    const float* bx     = (const float*)d_in[5];
    const float* bh     = (const float*)d_in[6];
    float* out = (float*)d_out;
    (void)in_sizes; (void)n_in;

    cudaFuncSetAttribute(lstm_persist, cudaFuncAttributeMaxDynamicSharedMemorySize, SM_TOTAL);

    reset_bar<<<1, 1>>>();
    pack_wp<<<(G4 * HH) / 256, 256>>>(Wh, 0);
    pack_wp<<<(G4 * HH) / 256, 256>>>(Wx, 1);
    pack_xb<<<(int)(((size_t)TT * BB * HH) / 256), 256>>>(input_);
    pack_h0<<<(BB * HH) / 256, 256>>>(h0);

    long long need = (long long)TT * BB * HH + 2LL * BB * HH;
    int full = (out_size >= need) ? 1 : 0;
    float* hfin = out + (size_t)TT * BB * HH;
    float* cfin = hfin + (size_t)BB * HH;

    lstm_persist<<<NCTA, 256, SM_TOTAL>>>(c0, bx, bh, out, hfin, cfin, full);
}

// round 9
// speedup vs baseline: 1.9415x; 1.9415x over previous
#include <cuda_runtime.h>
#include <cuda_fp16.h>
#include <math.h>
#include <stdint.h>

#define TT 512
#define BB 64
#define HH 1024
#define G4 4096
#define NCTA 128
#define WL 4          // gx lead window
#define RSLOTS 5      // smem ring slots

// ---------------- device scratch (static, no runtime alloc) ----------------
// Wh / Wx per-CTA A-frag blobs: [c128][mt2][kt64][lane32][reg4] fp16
static __device__ uint32_t g_whp[(size_t)NCTA * 16384];
static __device__ uint32_t g_wxp[(size_t)NCTA * 16384];
// X B-frag blob: [t512][kt64][nt8][lane32][reg2] fp16  (64 MB)
static __device__ uint32_t g_xb[(size_t)TT * 32768];
// h B-frag (double buffered): [buf2][kt64][nt8][lane32][reg2]
static __device__ uint32_t g_hfrag[2][32768];
static __device__ int g_arrive;

// ---------------- mma.sync m16n8k16 fp16 (base sm_80+) ----------------
__device__ __forceinline__ void mma16816(float* c, const uint32_t* a, const uint32_t* b) {
    asm volatile(
        "mma.sync.aligned.m16n8k16.row.col.f32.f16.f16.f32 "
        "{%0,%1,%2,%3}, {%4,%5,%6,%7}, {%8,%9}, {%0,%1,%2,%3};"
        : "+f"(c[0]), "+f"(c[1]), "+f"(c[2]), "+f"(c[3])
        : "r"(a[0]), "r"(a[1]), "r"(a[2]), "r"(a[3]), "r"(b[0]), "r"(b[1]));
}

// ---------------------------------------------------------------------------
// Pack kernels (layouts validated R3-R8). Destination chosen device-side.
// A (16x16): lane=((r&7)<<2)|((kk>>1)&3), reg=((kk>>3)<<1)|(r>>3), half=kk&1
// B (8x16):  lane=((n&7)<<2)|((kk>>1)&3), reg=kk>>3,               half=kk&1
// ---------------------------------------------------------------------------
__global__ __launch_bounds__(256) void pack_wp(const float* __restrict__ Wsrc,
                                               int which) {
    uint32_t* dst = which ? g_wxp : g_whp;
    int idx = blockIdx.x * 256 + threadIdx.x;   // 4096*1024
    int row = idx >> 10, k = idx & 1023;
    int g = row >> 10, u = row & 1023;
    int c = u >> 3, ul = u & 7;
    int rm = g * 8 + ul;                        // row within CTA's 32
    int mt = rm >> 4, r = rm & 15;
    int kt = k >> 4, kk = k & 15;
    int lane = ((r & 7) << 2) | ((kk >> 1) & 3);
    int reg = ((kk >> 3) << 1) | (r >> 3);
    int half = kk & 1;
    size_t base = (size_t)c * 16384 + ((size_t)mt * 64 + kt) * 128 + lane * 4 + reg;
    ((__half*)&dst[base])[half] = __float2half_rn(Wsrc[idx]);
}

__global__ __launch_bounds__(256) void pack_xb(const float* __restrict__ X) {
    size_t idx = (size_t)blockIdx.x * 256 + threadIdx.x;  // 512*64*1024
    int t = (int)(idx >> 16);
    int b = (int)(idx >> 10) & 63;
    int k = (int)(idx & 1023);
    int kt = k >> 4, kk = k & 15;
    int nt = b >> 3;
    int lane = ((b & 7) << 2) | ((kk >> 1) & 3);
    int reg = kk >> 3;
    int half = kk & 1;
    size_t wi = (size_t)t * 32768 + ((size_t)(kt * 8 + nt) * 32 + lane) * 2 + reg;
    ((__half*)&g_xb[wi])[half] = __float2half_rn(X[idx]);
}

__global__ __launch_bounds__(256) void pack_h0(const float* __restrict__ h0) {
    int idx = blockIdx.x * 256 + threadIdx.x;   // 64*1024
    int b = idx >> 10, u = idx & 1023;
    int kt = u >> 4, kk = u & 15;
    int nt = b >> 3;
    int lane = ((b & 7) << 2) | ((kk >> 1) & 3);
    int reg = kk >> 3;
    int half = kk & 1;
    size_t wi = ((size_t)(kt * 8 + nt) * 32 + lane) * 2 + reg;
    ((__half*)&g_hfrag[0][wi])[half] = __float2half_rn(h0[idx]);
}

__global__ void reset_bar() { g_arrive = 0; }

// ---------------------------------------------------------------------------
// Fused persistent kernel: 128 CTAs x 256 threads, 1 CTA/SM.
// CTA c owns cells [c*8, c*8+8) (32 gate rows).
// Rec GEMM: R6 layout — warp (mt=w>>2, q=w&3): 16 kts x 8 nts, MLP-8 loads,
//           K-partials in Gs[q]. Gx GEMM (for t+WL): warp w = nt, full M/K,
//           8-kt load batches, executed in the barrier shadow.
// ---------------------------------------------------------------------------
#define SO_WX   65536
#define SO_GS   131072                              // 4*32*68*4 = 34816
#define SO_RING (SO_GS + 34816)                     // 165888; 5*32*66*4 = 42240
#define SO_CS   (SO_RING + 42240)                   // 208128
#define SO_BS   (SO_CS + 2048)                      // 210176
#define SM_TOTAL (SO_BS + 128)                      // 210304

__global__ __launch_bounds__(256, 1) void lstm_persist(
    const float* __restrict__ c0,
    const float* __restrict__ bx, const float* __restrict__ bh,
    float* __restrict__ out,
    float* __restrict__ hfin, float* __restrict__ cfin,
    int full)
{
    extern __shared__ __align__(16) char sm[];
    uint32_t (*whs)[64][128] = (uint32_t (*)[64][128])sm;            // [mt][kt][lane*4+reg]
    uint32_t (*wxs)[64][128] = (uint32_t (*)[64][128])(sm + SO_WX);
    float (*Gs)[32][68] = (float (*)[32][68])(sm + SO_GS);
    float (*ring)[32][66] = (float (*)[32][66])(sm + SO_RING);
    float* cs = (float*)(sm + SO_CS);
    float* bsum = (float*)(sm + SO_BS);

    const int cta = blockIdx.x;
    const int tid = threadIdx.x;
    const int w = tid >> 5, lane = tid & 31;
    const int mt = w >> 2, q = w & 3;          // rec split
    const int r0q = lane >> 2;                 // fragment row offset
    const int c0q = (lane & 3) * 2;            // fragment col offset

    // ---- init ----
    {
        const uint4* s1 = (const uint4*)(g_whp + (size_t)cta * 16384);
        const uint4* s2 = (const uint4*)(g_wxp + (size_t)cta * 16384);
        uint4* d1 = (uint4*)sm;
        uint4* d2 = (uint4*)(sm + SO_WX);
        for (int i = tid; i < 4096; i += 256) { d1[i] = s1[i]; d2[i] = s2[i]; }
        for (int i = tid; i < 512; i += 256) {
            int b = i >> 3, ul = i & 7;
            cs[i] = c0[(size_t)b * HH + cta * 8 + ul];
        }
        if (tid < 32) {
            int g = tid >> 3, u = cta * 8 + (tid & 7);
            int col = g * HH + u;
            bsum[tid] = bx[col] + bh[col];
        }
    }
    __syncthreads();

    // ---- gx slice for timestep tw -> ring[slot]; warp w = nt; MLP-8 loads ----
    auto gx_slice = [&](int tw, int slot) {
        float ga[2][4];
#pragma unroll
        for (int i = 0; i < 2; i++)
#pragma unroll
            for (int j = 0; j < 4; j++) ga[i][j] = 0.f;
        const uint32_t* Bx = g_xb + (size_t)tw * 32768;
        for (int kg = 0; kg < 8; kg++) {
            uint2 bf[8];
#pragma unroll
            for (int j = 0; j < 8; j++) {
                int kt = kg * 8 + j;
                bf[j] = __ldcg((const uint2*)(Bx + (uint32_t)(kt * 8 + w) * 64 + lane * 2));
            }
#pragma unroll
            for (int j = 0; j < 8; j++) {
                int kt = kg * 8 + j;
                uint4 a0 = *(const uint4*)&wxs[0][kt][lane * 4];
                uint4 a1 = *(const uint4*)&wxs[1][kt][lane * 4];
                mma16816(ga[0], (const uint32_t*)&a0, (const uint32_t*)&bf[j]);
                mma16816(ga[1], (const uint32_t*)&a1, (const uint32_t*)&bf[j]);
            }
        }
        const int col = w * 8 + c0q;
#pragma unroll
        for (int m2 = 0; m2 < 2; m2++) {
            int ra = m2 * 16 + r0q;
            ring[slot][ra][col]     = ga[m2][0] + bsum[ra];
            ring[slot][ra][col + 1] = ga[m2][1] + bsum[ra];
            ring[slot][ra + 8][col]     = ga[m2][2] + bsum[ra + 8];
            ring[slot][ra + 8][col + 1] = ga[m2][3] + bsum[ra + 8];
        }
    };

    // lead-in: gx for t = 0..WL-1 into slots 0..WL-1
    for (int tw = 0; tw < WL; tw++) gx_slice(tw, tw);

    for (int t = 0; t < TT; t++) {
        // ---- rec GEMM (R6 structure): D[32,64] = Wh_slice @ h[t] ----
        float acc[8][4];
#pragma unroll
        for (int i = 0; i < 8; i++)
#pragma unroll
            for (int j = 0; j < 4; j++) acc[i][j] = 0.f;
        const uint32_t* Bf = &g_hfrag[t & 1][0];
        const int kt0 = q * 16;
#pragma unroll 4
        for (int kt = kt0; kt < kt0 + 16; kt++) {
            uint4 a_v = *(const uint4*)&whs[mt][kt][lane * 4];
            const uint32_t* a = (const uint32_t*)&a_v;
            uint2 bf[8];
#pragma unroll
            for (int nt = 0; nt < 8; nt++) {
                uint32_t off = (uint32_t)(kt * 8 + nt) * 64 + lane * 2;
                bf[nt] = __ldcg((const uint2*)(Bf + off));
            }
#pragma unroll
            for (int nt = 0; nt < 8; nt++) mma16816(acc[nt], a, (const uint32_t*)&bf[nt]);
        }

        // ---- scatter partials: Gs[q][row32][b] ----
        {
            const int r0 = mt * 16 + r0q;
#pragma unroll
            for (int nt = 0; nt < 8; nt++) {
                int col = nt * 8 + c0q;
                Gs[q][r0][col]     = acc[nt][0];
                Gs[q][r0][col + 1] = acc[nt][1];
                Gs[q][r0 + 8][col]     = acc[nt][2];
                Gs[q][r0 + 8][col + 1] = acc[nt][3];
            }
        }
        __syncthreads();

        // ---- cell update: 2 cells per thread ----
        const int slot = t % RSLOTS;
        float* outt = out + (size_t)t * BB * HH;
        const int nb = (t + 1) & 1;
        float hsave[2], csave[2];
#pragma unroll
        for (int pp = 0; pp < 2; pp++) {
            const int p = tid + pp * 256;
            const int b = p >> 3, ul = p & 7;
            const int u = cta * 8 + ul;

            float x0 = Gs[0][ul][b] + Gs[1][ul][b] + Gs[2][ul][b] + Gs[3][ul][b]
                       + ring[slot][ul][b];
            float x1 = Gs[0][8 + ul][b] + Gs[1][8 + ul][b] + Gs[2][8 + ul][b] + Gs[3][8 + ul][b]
                       + ring[slot][8 + ul][b];
            float x2 = Gs[0][16 + ul][b] + Gs[1][16 + ul][b] + Gs[2][16 + ul][b] + Gs[3][16 + ul][b]
                       + ring[slot][16 + ul][b];
            float x3 = Gs[0][24 + ul][b] + Gs[1][24 + ul][b] + Gs[2][24 + ul][b] + Gs[3][24 + ul][b]
                       + ring[slot][24 + ul][b];

            float ig = 1.f / (1.f + __expf(-x0));
            float fg = 1.f / (1.f + __expf(-x1));
            float og = 1.f / (1.f + __expf(-x2));
            float ng = tanhf(x3);

            float cprev = cs[p];
            float cnew = fg * cprev + ig * ng;
            float hnew = og * tanhf(cnew);
            cs[p] = cnew;
            hsave[pp] = hnew;
            csave[pp] = cnew;

            // publish next-step B fragment (fp16)
            int kt = u >> 4, kk = u & 15, nt = b >> 3;
            int lt = ((b & 7) << 2) | ((kk >> 1) & 3);
            int rg = kk >> 3, hf = kk & 1;
            size_t wi = ((size_t)(kt * 8 + nt) * 32 + lt) * 2 + rg;
            ((__half*)&g_hfrag[nb][wi])[hf] = __float2half_rn(hnew);

            if (t == TT - 1 && full) {
                hfin[(size_t)b * HH + u] = hnew;
                cfin[(size_t)b * HH + u] = cnew;
            }
        }

        // ---- barrier arrive (R6 pattern), then barrier-shadow work ----
        __threadfence();
        __syncthreads();
        if (tid == 0) atomicAdd(&g_arrive, 1);

        // shadow 1: output stores (not consumed by anyone this pass)
#pragma unroll
        for (int pp = 0; pp < 2; pp++) {
            const int p = tid + pp * 256;
            const int b = p >> 3, ul = p & 7;
            outt[(size_t)b * HH + cta * 8 + ul] = hsave[pp];
        }

        // shadow 2: gx GEMM for t+WL (independent of other CTAs; hides skew)
        if (t + WL < TT) gx_slice(t + WL, (t + WL) % RSLOTS);

        // barrier wait
        if (tid == 0) {
            volatile int* va = &g_arrive;
            while (*va < NCTA * (t + 1)) __nanosleep(32);
        }
        __syncthreads();
    }
}

// ---------------------------------------------------------------------------
extern "C" void kernel_launch(void* const* d_in, const int* in_sizes, int n_in,
                              void* d_out, int out_size)
{
    const float* input_ = (const float*)d_in[0];
    const float* h0     = (const float*)d_in[1];
    const float* c0     = (const float*)d_in[2];
    const float* Wx     = (const float*)d_in[3];
    const float* Wh     = (const float*)d_in[4];
    const float* bx     = (const float*)d_in[5];
    const float* bh     = (const float*)d_in[6];
    float* out = (float*)d_out;
    (void)in_sizes; (void)n_in;

    cudaFuncSetAttribute(lstm_persist, cudaFuncAttributeMaxDynamicSharedMemorySize, SM_TOTAL);

    reset_bar<<<1, 1>>>();
    pack_wp<<<(G4 * HH) / 256, 256>>>(Wh, 0);
    pack_wp<<<(G4 * HH) / 256, 256>>>(Wx, 1);
    pack_xb<<<(int)(((size_t)TT * BB * HH) / 256), 256>>>(input_);
    pack_h0<<<(BB * HH) / 256, 256>>>(h0);

    long long need = (long long)TT * BB * HH + 2LL * BB * HH;
    int full = (out_size >= need) ? 1 : 0;
    float* hfin = out + (size_t)TT * BB * HH;
    float* cfin = hfin + (size_t)BB * HH;

    lstm_persist<<<NCTA, 256, SM_TOTAL>>>(c0, bx, bh, out, hfin, cfin, full);
}

// round 10
// speedup vs baseline: 2.1236x; 1.0938x over previous
#include <cuda_runtime.h>
#include <cuda_fp16.h>
#include <math.h>
#include <stdint.h>

#define TT 512
#define BB 64
#define HH 1024
#define G4 4096
#define NCTA 128

// ---------------- device scratch (static, no runtime alloc) ----------------
static __device__ float g_gx[(size_t)TT * BB * G4];        // fp32: X@Wx^T + bx + bh
// Wh per-CTA A-frag blob: [c128][mt2][kt64][lane32][reg4] fp16
static __device__ uint32_t g_whp[(size_t)NCTA * 16384];
// Wx B-frag: [nt512][kt64][lane32][reg2] fp16
static __device__ uint32_t g_wxfrag[(size_t)512 * 64 * 64];
// X A-frag: [mt2048][kt64][lane32][reg4] fp16
static __device__ uint32_t g_xfrag[(size_t)2048 * 64 * 128];
// h B-frag (double buffered): [buf2][kt64][nt8][lane32][reg2]
static __device__ uint32_t g_hfrag[2][32768];
static __device__ int g_arrive;

// ---------------- mma.sync m16n8k16 fp16 (base sm_80+) ----------------
__device__ __forceinline__ void mma16816(float* c, const uint32_t* a, const uint32_t* b) {
    asm volatile(
        "mma.sync.aligned.m16n8k16.row.col.f32.f16.f16.f32 "
        "{%0,%1,%2,%3}, {%4,%5,%6,%7}, {%8,%9}, {%0,%1,%2,%3};"
        : "+f"(c[0]), "+f"(c[1]), "+f"(c[2]), "+f"(c[3])
        : "r"(a[0]), "r"(a[1]), "r"(a[2]), "r"(a[3]), "r"(b[0]), "r"(b[1]));
}

__device__ __forceinline__ void bar_release_add(int* p) {
    asm volatile("red.release.gpu.global.add.s32 [%0], 1;" :: "l"(p) : "memory");
}
__device__ __forceinline__ int bar_acquire_ld(const int* p) {
    int v;
    asm volatile("ld.acquire.gpu.global.s32 %0, [%1];" : "=r"(v) : "l"(p) : "memory");
    return v;
}

// ---------------------------------------------------------------------------
// Pack kernels (layouts validated R3-R9).
// A (16x16): lane=((r&7)<<2)|((kk>>1)&3), reg=((kk>>3)<<1)|(r>>3), half=kk&1
// B (8x16):  lane=((n&7)<<2)|((kk>>1)&3), reg=kk>>3,               half=kk&1
// ---------------------------------------------------------------------------
__global__ __launch_bounds__(256) void pack_whp(const float* __restrict__ Wh) {
    int idx = blockIdx.x * 256 + threadIdx.x;   // 4096*1024
    int row = idx >> 10, k = idx & 1023;
    int g = row >> 10, u = row & 1023;
    int c = u >> 3, ul = u & 7;
    int rm = g * 8 + ul;                        // row within CTA's 32
    int mt = rm >> 4, r = rm & 15;
    int kt = k >> 4, kk = k & 15;
    int lane = ((r & 7) << 2) | ((kk >> 1) & 3);
    int reg = ((kk >> 3) << 1) | (r >> 3);
    int half = kk & 1;
    size_t base = (size_t)c * 16384 + ((size_t)mt * 64 + kt) * 128 + lane * 4 + reg;
    ((__half*)&g_whp[base])[half] = __float2half_rn(Wh[idx]);
}

__global__ __launch_bounds__(256) void pack_wx(const float* __restrict__ Wx) {
    int idx = blockIdx.x * 256 + threadIdx.x;   // 4096*1024
    int n = idx >> 10, k = idx & 1023;
    int nt = n >> 3, nl = n & 7;
    int kt = k >> 4, kk = k & 15;
    int lane = (nl << 2) | ((kk >> 1) & 3);
    int reg = kk >> 3;
    int half = kk & 1;
    size_t wi = ((size_t)(nt * 64 + kt) * 32 + lane) * 2 + reg;
    ((__half*)&g_wxfrag[wi])[half] = __float2half_rn(Wx[idx]);
}

__global__ __launch_bounds__(256) void pack_x(const float* __restrict__ X) {
    size_t idx = (size_t)blockIdx.x * 256 + threadIdx.x;  // 32768*1024
    int row = (int)(idx >> 10), k = (int)(idx & 1023);
    int mt = row >> 4, r = row & 15;
    int kt = k >> 4, kk = k & 15;
    int lane = ((r & 7) << 2) | ((kk >> 1) & 3);
    int reg = ((kk >> 3) << 1) | (r >> 3);
    int half = kk & 1;
    size_t wi = (((size_t)mt * 64 + kt) * 32 + lane) * 4 + reg;
    ((__half*)&g_xfrag[wi])[half] = __float2half_rn(X[idx]);
}

__global__ __launch_bounds__(256) void pack_h0(const float* __restrict__ h0) {
    int idx = blockIdx.x * 256 + threadIdx.x;   // 64*1024
    int b = idx >> 10, u = idx & 1023;
    int kt = u >> 4, kk = u & 15;
    int nt = b >> 3;
    int lane = ((b & 7) << 2) | ((kk >> 1) & 3);
    int reg = kk >> 3;
    int half = kk & 1;
    size_t wi = ((size_t)(kt * 8 + nt) * 32 + lane) * 2 + reg;
    ((__half*)&g_hfrag[0][wi])[half] = __float2half_rn(h0[idx]);
}

__global__ void reset_bar() { g_arrive = 0; }

// ---------------------------------------------------------------------------
// gx GEMM (R6 verbatim, at the HMMA floor): gx = X@Wx^T + bx + bh
// ---------------------------------------------------------------------------
__global__ __launch_bounds__(256) void gx_mma_kernel(
    const float* __restrict__ bx, const float* __restrict__ bh)
{
    const int tid = threadIdx.x;
    const int wid = tid >> 5, lane = tid & 31;
    const int wm = wid & 1, wn = wid >> 1;
    const int mtb = blockIdx.y * 8 + wm * 4;
    const int ntb = blockIdx.x * 16 + wn * 4;

    float acc[4][4][4];
#pragma unroll
    for (int i = 0; i < 4; i++)
#pragma unroll
        for (int j = 0; j < 4; j++)
#pragma unroll
            for (int q = 0; q < 4; q++) acc[i][j][q] = 0.f;

    const uint32_t* Af = g_xfrag + (size_t)lane * 4;
    const uint32_t* Bf = g_wxfrag + (size_t)lane * 2;

#pragma unroll 2
    for (int kt = 0; kt < 64; kt++) {
        uint32_t b_f[4][2];
#pragma unroll
        for (int nt = 0; nt < 4; nt++) {
            size_t bo = (size_t)((ntb + nt) * 64 + kt) * 64;
            *(uint2*)b_f[nt] = *(const uint2*)(Bf + bo);
        }
#pragma unroll
        for (int mt = 0; mt < 4; mt++) {
            size_t ao = ((size_t)(mtb + mt) * 64 + kt) * 128;
            uint32_t a[4];
            *(uint4*)a = *(const uint4*)(Af + ao);
#pragma unroll
            for (int nt = 0; nt < 4; nt++)
                mma16816(acc[mt][nt], a, b_f[nt]);
        }
    }

#pragma unroll
    for (int mt = 0; mt < 4; mt++) {
        int row = (mtb + mt) * 16 + (lane >> 2);
#pragma unroll
        for (int nt = 0; nt < 4; nt++) {
            int col = (ntb + nt) * 8 + (lane & 3) * 2;
            float bb0 = bx[col] + bh[col];
            float bb1 = bx[col + 1] + bh[col + 1];
            float2 v0 = make_float2(acc[mt][nt][0] + bb0, acc[mt][nt][1] + bb1);
            float2 v1 = make_float2(acc[mt][nt][2] + bb0, acc[mt][nt][3] + bb1);
            *(float2*)(g_gx + (size_t)row * G4 + col) = v0;
            *(float2*)(g_gx + (size_t)(row + 8) * G4 + col) = v1;
        }
    }
}

// ---------------------------------------------------------------------------
// Persistent recurrence: 128 CTAs x 256 threads, 1 CTA/SM.
// CTA c owns cells [c*8, c*8+8) (32 gate rows: gate g = rows g*8..g*8+7).
// Warp w = nt (batch cols w*8..w*8+8), both mtiles, full K. The C-fragment
// places all 4 gates of cells (b0,u),(b1,u) in ONE thread:
//   u = cta*8 + (lane>>2); b0 = w*8 + (lane&3)*2; b1 = b0+1
//   gate i/f = acc[0][0|1]/acc[0][2|3]; gate o/n = acc[1][0|1]/acc[1][2|3]
// => register-resident epilogue, no smem exchange, no mid-step syncthreads.
// Cell state lives in registers. Barrier: sync -> tid0 release-add -> per-warp
// acquire poll; out stores in the poll shadow.
// ---------------------------------------------------------------------------
#define SM_TOTAL 65536

__global__ __launch_bounds__(256, 1) void lstm_rec(
    const float* __restrict__ c0,
    float* __restrict__ out,
    float* __restrict__ hfin, float* __restrict__ cfin,
    int full)
{
    extern __shared__ __align__(16) char sm[];
    uint32_t (*whs)[64][128] = (uint32_t (*)[64][128])sm;   // [mt][kt][lane*4+reg]

    const int cta = blockIdx.x;
    const int tid = threadIdx.x;
    const int w = tid >> 5, lane = tid & 31;
    const int ul = lane >> 2;
    const int b0 = w * 8 + (lane & 3) * 2;
    const int b1 = b0 + 1;
    const int u = cta * 8 + ul;

    // ---- init: Wh slice -> smem; cell state -> registers ----
    {
        const uint4* src = (const uint4*)(g_whp + (size_t)cta * 16384);
        uint4* dst = (uint4*)sm;
        for (int i = tid; i < 4096; i += 256) dst[i] = src[i];
    }
    float creg0 = c0[(size_t)b0 * HH + u];
    float creg1 = c0[(size_t)b1 * HH + u];

    // precompute h-frag publish indices for (b0,u), (b1,u)
    const int pkt = u >> 4, pkk = u & 15;
    const int prg = pkk >> 3, phf = pkk & 1;
    const int pnt = b0 >> 3;
    const int plt0 = ((b0 & 7) << 2) | ((pkk >> 1) & 3);
    const int plt1 = ((b1 & 7) << 2) | ((pkk >> 1) & 3);
    const size_t pw0 = ((size_t)(pkt * 8 + pnt) * 32 + plt0) * 2 + prg;
    const size_t pw1 = ((size_t)(pkt * 8 + pnt) * 32 + plt1) * 2 + prg;

    __syncthreads();

    for (int t = 0; t < TT; t++) {
        // ---- prefetch gate pre-activations (consumed in epilogue) ----
        const float* gxr0 = g_gx + ((size_t)t * BB + b0) * G4 + u;
        const float* gxr1 = g_gx + ((size_t)t * BB + b1) * G4 + u;
        float gp0[4], gp1[4];
#pragma unroll
        for (int g = 0; g < 4; g++) {
            gp0[g] = __ldcg(gxr0 + g * HH);
            gp1[g] = __ldcg(gxr1 + g * HH);
        }

        // ---- rec GEMM: acc[mt][4] over full K, batched MLP-8 loads ----
        float acc[2][4];
#pragma unroll
        for (int i = 0; i < 2; i++)
#pragma unroll
            for (int j = 0; j < 4; j++) acc[i][j] = 0.f;
        const uint32_t* Bf = &g_hfrag[t & 1][0];
        for (int kg = 0; kg < 8; kg++) {
            uint2 bf[8];
#pragma unroll
            for (int j = 0; j < 8; j++) {
                int kt = kg * 8 + j;
                bf[j] = __ldcg((const uint2*)(Bf + (uint32_t)(kt * 8 + w) * 64 + lane * 2));
            }
#pragma unroll
            for (int j = 0; j < 8; j++) {
                int kt = kg * 8 + j;
                uint4 a0 = *(const uint4*)&whs[0][kt][lane * 4];
                uint4 a1 = *(const uint4*)&whs[1][kt][lane * 4];
                mma16816(acc[0], (const uint32_t*)&a0, (const uint32_t*)&bf[j]);
                mma16816(acc[1], (const uint32_t*)&a1, (const uint32_t*)&bf[j]);
            }
        }

        // ---- register-resident cell update (both cells in this thread) ----
        float x0a = acc[0][0] + gp0[0];   // gate i, b0
        float x1a = acc[0][2] + gp0[1];   // gate f, b0
        float x2a = acc[1][0] + gp0[2];   // gate o, b0
        float x3a = acc[1][2] + gp0[3];   // gate n, b0
        float x0b = acc[0][1] + gp1[0];
        float x1b = acc[0][3] + gp1[1];
        float x2b = acc[1][1] + gp1[2];
        float x3b = acc[1][3] + gp1[3];

        float iga = 1.f / (1.f + __expf(-x0a));
        float fga = 1.f / (1.f + __expf(-x1a));
        float oga = 1.f / (1.f + __expf(-x2a));
        float nga = tanhf(x3a);
        float igb = 1.f / (1.f + __expf(-x0b));
        float fgb = 1.f / (1.f + __expf(-x1b));
        float ogb = 1.f / (1.f + __expf(-x2b));
        float ngb = tanhf(x3b);

        creg0 = fga * creg0 + iga * nga;
        creg1 = fgb * creg1 + igb * ngb;
        float h0v = oga * tanhf(creg0);
        float h1v = ogb * tanhf(creg1);

        // ---- publish next-step h fragments (fp16) ----
        const int nb = (t + 1) & 1;
        ((__half*)&g_hfrag[nb][pw0])[phf] = __float2half_rn(h0v);
        ((__half*)&g_hfrag[nb][pw1])[phf] = __float2half_rn(h1v);

        // ---- barrier: all publishes done -> release; poll in shadow ----
        __syncthreads();
        if (tid == 0) bar_release_add(&g_arrive);

        // shadow: output stores (consumed only by harness after kernel end)
        float* outt = out + (size_t)t * BB * HH;
        outt[(size_t)b0 * HH + u] = h0v;
        outt[(size_t)b1 * HH + u] = h1v;
        if (t == TT - 1 && full) {
            hfin[(size_t)b0 * HH + u] = h0v;
            hfin[(size_t)b1 * HH + u] = h1v;
            cfin[(size_t)b0 * HH + u] = creg0;
            cfin[(size_t)b1 * HH + u] = creg1;
        }

        // per-warp acquire poll (no trailing CTA sync needed)
        if (lane == 0) {
            const int target = NCTA * (t + 1);
            while (bar_acquire_ld(&g_arrive) < target) { }
        }
        __syncwarp();
    }
}

// ---------------------------------------------------------------------------
extern "C" void kernel_launch(void* const* d_in, const int* in_sizes, int n_in,
                              void* d_out, int out_size)
{
    const float* input_ = (const float*)d_in[0];
    const float* h0     = (const float*)d_in[1];
    const float* c0     = (const float*)d_in[2];
    const float* Wx     = (const float*)d_in[3];
    const float* Wh     = (const float*)d_in[4];
    const float* bx     = (const float*)d_in[5];
    const float* bh     = (const float*)d_in[6];
    float* out = (float*)d_out;
    (void)in_sizes; (void)n_in;

    cudaFuncSetAttribute(lstm_rec, cudaFuncAttributeMaxDynamicSharedMemorySize, SM_TOTAL);

    reset_bar<<<1, 1>>>();
    pack_whp<<<(G4 * HH) / 256, 256>>>(Wh);
    pack_wx<<<(G4 * HH) / 256, 256>>>(Wx);
    pack_x<<<(int)(((size_t)TT * BB * HH) / 256), 256>>>(input_);
    pack_h0<<<(BB * HH) / 256, 256>>>(h0);

    dim3 ggrid(G4 / 128, (TT * BB) / 128);
    gx_mma_kernel<<<ggrid, 256>>>(bx, bh);

    long long need = (long long)TT * BB * HH + 2LL * BB * HH;
    int full = (out_size >= need) ? 1 : 0;
    float* hfin = out + (size_t)TT * BB * HH;
    float* cfin = hfin + (size_t)BB * HH;

    lstm_rec<<<NCTA, 256, SM_TOTAL>>>(c0, out, hfin, cfin, full);
}

// round 11
// speedup vs baseline: 2.4695x; 1.1629x over previous
#include <cuda_runtime.h>
#include <cuda_fp16.h>
#include <math.h>
#include <stdint.h>

#define TT 512
#define BB 64
#define HH 1024
#define G4 4096
#define NCTA 128

// ---------------- device scratch (static, no runtime alloc) ----------------
static __device__ float g_gx[(size_t)TT * BB * G4];        // fp32: X@Wx^T + bx + bh
// Wh per-CTA A-frag blob: [c128][mt2][kt64][lane32][reg4] fp16
static __device__ uint32_t g_whp[(size_t)NCTA * 16384];
// Wx B-frag: [nt512][kt64][lane32][reg2] fp16
static __device__ uint32_t g_wxfrag[(size_t)512 * 64 * 64];
// X A-frag: [mt2048][kt64][lane32][reg4] fp16
static __device__ uint32_t g_xfrag[(size_t)2048 * 64 * 128];
// h B-frag (double buffered): [buf2][kt64][nt8][lane32][reg2]
static __device__ uint32_t g_hfrag[2][32768];
static __device__ int g_arrive;

// ---------------- mma.sync m16n8k16 fp16 (base sm_80+) ----------------
__device__ __forceinline__ void mma16816(float* c, const uint32_t* a, const uint32_t* b) {
    asm volatile(
        "mma.sync.aligned.m16n8k16.row.col.f32.f16.f16.f32 "
        "{%0,%1,%2,%3}, {%4,%5,%6,%7}, {%8,%9}, {%0,%1,%2,%3};"
        : "+f"(c[0]), "+f"(c[1]), "+f"(c[2]), "+f"(c[3])
        : "r"(a[0]), "r"(a[1]), "r"(a[2]), "r"(a[3]), "r"(b[0]), "r"(b[1]));
}

__device__ __forceinline__ void bar_release_add(int* p) {
    asm volatile("red.release.gpu.global.add.s32 [%0], 1;" :: "l"(p) : "memory");
}
__device__ __forceinline__ int bar_acquire_ld(const int* p) {
    int v;
    asm volatile("ld.acquire.gpu.global.s32 %0, [%1];" : "=r"(v) : "l"(p) : "memory");
    return v;
}

// ---------------------------------------------------------------------------
// Pack kernels (layouts validated R3-R10).
// A (16x16): lane=((r&7)<<2)|((kk>>1)&3), reg=((kk>>3)<<1)|(r>>3), half=kk&1
// B (8x16):  lane=((n&7)<<2)|((kk>>1)&3), reg=kk>>3,               half=kk&1
// ---------------------------------------------------------------------------
__global__ __launch_bounds__(256) void pack_whp(const float* __restrict__ Wh) {
    int idx = blockIdx.x * 256 + threadIdx.x;   // 4096*1024
    int row = idx >> 10, k = idx & 1023;
    int g = row >> 10, u = row & 1023;
    int c = u >> 3, ul = u & 7;
    int rm = g * 8 + ul;                        // row within CTA's 32
    int mt = rm >> 4, r = rm & 15;
    int kt = k >> 4, kk = k & 15;
    int lane = ((r & 7) << 2) | ((kk >> 1) & 3);
    int reg = ((kk >> 3) << 1) | (r >> 3);
    int half = kk & 1;
    size_t base = (size_t)c * 16384 + ((size_t)mt * 64 + kt) * 128 + lane * 4 + reg;
    ((__half*)&g_whp[base])[half] = __float2half_rn(Wh[idx]);
}

__global__ __launch_bounds__(256) void pack_wx(const float* __restrict__ Wx) {
    int idx = blockIdx.x * 256 + threadIdx.x;   // 4096*1024
    int n = idx >> 10, k = idx & 1023;
    int nt = n >> 3, nl = n & 7;
    int kt = k >> 4, kk = k & 15;
    int lane = (nl << 2) | ((kk >> 1) & 3);
    int reg = kk >> 3;
    int half = kk & 1;
    size_t wi = ((size_t)(nt * 64 + kt) * 32 + lane) * 2 + reg;
    ((__half*)&g_wxfrag[wi])[half] = __float2half_rn(Wx[idx]);
}

__global__ __launch_bounds__(256) void pack_x(const float* __restrict__ X) {
    size_t idx = (size_t)blockIdx.x * 256 + threadIdx.x;  // 32768*1024
    int row = (int)(idx >> 10), k = (int)(idx & 1023);
    int mt = row >> 4, r = row & 15;
    int kt = k >> 4, kk = k & 15;
    int lane = ((r & 7) << 2) | ((kk >> 1) & 3);
    int reg = ((kk >> 3) << 1) | (r >> 3);
    int half = kk & 1;
    size_t wi = (((size_t)mt * 64 + kt) * 32 + lane) * 4 + reg;
    ((__half*)&g_xfrag[wi])[half] = __float2half_rn(X[idx]);
}

__global__ __launch_bounds__(256) void pack_h0(const float* __restrict__ h0) {
    int idx = blockIdx.x * 256 + threadIdx.x;   // 64*1024
    int b = idx >> 10, u = idx & 1023;
    int kt = u >> 4, kk = u & 15;
    int nt = b >> 3;
    int lane = ((b & 7) << 2) | ((kk >> 1) & 3);
    int reg = kk >> 3;
    int half = kk & 1;
    size_t wi = ((size_t)(kt * 8 + nt) * 32 + lane) * 2 + reg;
    ((__half*)&g_hfrag[0][wi])[half] = __float2half_rn(h0[idx]);
}

__global__ void reset_bar() { g_arrive = 0; }

// ---------------------------------------------------------------------------
// gx GEMM (R6 verbatim, at the HMMA floor): gx = X@Wx^T + bx + bh
// ---------------------------------------------------------------------------
__global__ __launch_bounds__(256) void gx_mma_kernel(
    const float* __restrict__ bx, const float* __restrict__ bh)
{
    const int tid = threadIdx.x;
    const int wid = tid >> 5, lane = tid & 31;
    const int wm = wid & 1, wn = wid >> 1;
    const int mtb = blockIdx.y * 8 + wm * 4;
    const int ntb = blockIdx.x * 16 + wn * 4;

    float acc[4][4][4];
#pragma unroll
    for (int i = 0; i < 4; i++)
#pragma unroll
        for (int j = 0; j < 4; j++)
#pragma unroll
            for (int q = 0; q < 4; q++) acc[i][j][q] = 0.f;

    const uint32_t* Af = g_xfrag + (size_t)lane * 4;
    const uint32_t* Bf = g_wxfrag + (size_t)lane * 2;

#pragma unroll 2
    for (int kt = 0; kt < 64; kt++) {
        uint32_t b_f[4][2];
#pragma unroll
        for (int nt = 0; nt < 4; nt++) {
            size_t bo = (size_t)((ntb + nt) * 64 + kt) * 64;
            *(uint2*)b_f[nt] = *(const uint2*)(Bf + bo);
        }
#pragma unroll
        for (int mt = 0; mt < 4; mt++) {
            size_t ao = ((size_t)(mtb + mt) * 64 + kt) * 128;
            uint32_t a[4];
            *(uint4*)a = *(const uint4*)(Af + ao);
#pragma unroll
            for (int nt = 0; nt < 4; nt++)
                mma16816(acc[mt][nt], a, b_f[nt]);
        }
    }

#pragma unroll
    for (int mt = 0; mt < 4; mt++) {
        int row = (mtb + mt) * 16 + (lane >> 2);
#pragma unroll
        for (int nt = 0; nt < 4; nt++) {
            int col = (ntb + nt) * 8 + (lane & 3) * 2;
            float bb0 = bx[col] + bh[col];
            float bb1 = bx[col + 1] + bh[col + 1];
            float2 v0 = make_float2(acc[mt][nt][0] + bb0, acc[mt][nt][1] + bb1);
            float2 v1 = make_float2(acc[mt][nt][2] + bb0, acc[mt][nt][3] + bb1);
            *(float2*)(g_gx + (size_t)row * G4 + col) = v0;
            *(float2*)(g_gx + (size_t)(row + 8) * G4 + col) = v1;
        }
    }
}

// ---------------------------------------------------------------------------
// Persistent recurrence: 128 CTAs x 256 threads, 1 CTA/SM.
// CTA c owns cells [c*8, c*8+8) (32 gate rows).
// Warp w = (q = w&3, nh = w>>2): K-quarter q, nt range nh*4..nh*4+3, BOTH mt.
// => each h B-fragment loaded exactly once per CTA (16 MB/step chip-wide),
//    A smem 128KB/CTA/step, 16 MMAs per kt vs 4 B loads, 8 acc chains.
// K-partials exchanged via Gs[q] (R6 pattern); cell state in smem.
// Barrier: syncthreads -> tid0 red.release -> out stores in shadow ->
//          tid0 acquire-poll w/ nanosleep -> syncthreads.
// ---------------------------------------------------------------------------
#define SO_GS   65536                        // 4*32*68*4 = 34816
#define SO_CS   (SO_GS + 34816)              // 100352
#define SM_TOTAL (SO_CS + 2048)              // 102400

__global__ __launch_bounds__(256, 1) void lstm_rec(
    const float* __restrict__ c0,
    float* __restrict__ out,
    float* __restrict__ hfin, float* __restrict__ cfin,
    int full)
{
    extern __shared__ __align__(16) char sm[];
    uint32_t (*whs)[64][128] = (uint32_t (*)[64][128])sm;   // [mt][kt][lane*4+reg]
    float (*Gs)[32][68] = (float (*)[32][68])(sm + SO_GS);
    float* cs = (float*)(sm + SO_CS);

    const int cta = blockIdx.x;
    const int tid = threadIdx.x;
    const int w = tid >> 5, lane = tid & 31;
    const int q = w & 3, nh = w >> 2;
    const int r0q = lane >> 2;
    const int c0q = (lane & 3) * 2;

    // ---- init: Wh slice -> smem; cell state -> smem ----
    {
        const uint4* src = (const uint4*)(g_whp + (size_t)cta * 16384);
        uint4* dst = (uint4*)sm;
        for (int i = tid; i < 4096; i += 256) dst[i] = src[i];
        for (int i = tid; i < 512; i += 256) {
            int b = i >> 3, ul = i & 7;
            cs[i] = c0[(size_t)b * HH + cta * 8 + ul];
        }
    }
    __syncthreads();

    for (int t = 0; t < TT; t++) {
        // ---- prefetch gate pre-activations (hidden under GEMM) ----
        float gpre[2][4];
#pragma unroll
        for (int pp = 0; pp < 2; pp++) {
            const int p = tid + pp * 256;
            const int b = p >> 3, ul = p & 7;
            const float* gxr = g_gx + ((size_t)t * BB + b) * G4 + cta * 8 + ul;
#pragma unroll
            for (int g = 0; g < 4; g++) gpre[pp][g] = __ldcg(gxr + g * HH);
        }

        // ---- rec GEMM: warp covers (q, nh), both mt; acc[mt][ntl][4] ----
        float acc[2][4][4];
#pragma unroll
        for (int i = 0; i < 2; i++)
#pragma unroll
            for (int j = 0; j < 4; j++)
#pragma unroll
                for (int r = 0; r < 4; r++) acc[i][j][r] = 0.f;

        const uint32_t* Bf = &g_hfrag[t & 1][0];
        const int kt0 = q * 16;
#pragma unroll 4
        for (int kt = kt0; kt < kt0 + 16; kt++) {
            uint2 bf[4];
#pragma unroll
            for (int ntl = 0; ntl < 4; ntl++) {
                uint32_t off = (uint32_t)(kt * 8 + nh * 4 + ntl) * 64 + lane * 2;
                bf[ntl] = __ldcg((const uint2*)(Bf + off));
            }
            uint4 a0v = *(const uint4*)&whs[0][kt][lane * 4];
            uint4 a1v = *(const uint4*)&whs[1][kt][lane * 4];
            const uint32_t* a0 = (const uint32_t*)&a0v;
            const uint32_t* a1 = (const uint32_t*)&a1v;
#pragma unroll
            for (int ntl = 0; ntl < 4; ntl++) {
                mma16816(acc[0][ntl], a0, (const uint32_t*)&bf[ntl]);
                mma16816(acc[1][ntl], a1, (const uint32_t*)&bf[ntl]);
            }
        }

        // ---- scatter partials: Gs[q][row32][b] ----
#pragma unroll
        for (int mt = 0; mt < 2; mt++) {
            const int rbase = mt * 16 + r0q;
#pragma unroll
            for (int ntl = 0; ntl < 4; ntl++) {
                int col = (nh * 4 + ntl) * 8 + c0q;
                Gs[q][rbase][col]     = acc[mt][ntl][0];
                Gs[q][rbase][col + 1] = acc[mt][ntl][1];
                Gs[q][rbase + 8][col]     = acc[mt][ntl][2];
                Gs[q][rbase + 8][col + 1] = acc[mt][ntl][3];
            }
        }
        __syncthreads();

        // ---- cell update: 2 cells per thread ----
        float* outt = out + (size_t)t * BB * HH;
        const int nb = (t + 1) & 1;
        float hsave[2], csave[2];
#pragma unroll
        for (int pp = 0; pp < 2; pp++) {
            const int p = tid + pp * 256;
            const int b = p >> 3, ul = p & 7;
            const int u = cta * 8 + ul;

            float x0 = Gs[0][ul][b] + Gs[1][ul][b] + Gs[2][ul][b] + Gs[3][ul][b] + gpre[pp][0];
            float x1 = Gs[0][8 + ul][b] + Gs[1][8 + ul][b] + Gs[2][8 + ul][b] + Gs[3][8 + ul][b] + gpre[pp][1];
            float x2 = Gs[0][16 + ul][b] + Gs[1][16 + ul][b] + Gs[2][16 + ul][b] + Gs[3][16 + ul][b] + gpre[pp][2];
            float x3 = Gs[0][24 + ul][b] + Gs[1][24 + ul][b] + Gs[2][24 + ul][b] + Gs[3][24 + ul][b] + gpre[pp][3];

            float ig = 1.f / (1.f + __expf(-x0));
            float fg = 1.f / (1.f + __expf(-x1));
            float og = 1.f / (1.f + __expf(-x2));
            float ng = tanhf(x3);

            float cprev = cs[p];
            float cnew = fg * cprev + ig * ng;
            float hnew = og * tanhf(cnew);
            cs[p] = cnew;
            hsave[pp] = hnew;
            csave[pp] = cnew;

            // publish next-step B fragment (fp16)
            int kt = u >> 4, kk = u & 15, nt = b >> 3;
            int lt = ((b & 7) << 2) | ((kk >> 1) & 3);
            int rg = kk >> 3, hf = kk & 1;
            size_t wi = ((size_t)(kt * 8 + nt) * 32 + lt) * 2 + rg;
            ((__half*)&g_hfrag[nb][wi])[hf] = __float2half_rn(hnew);

            if (t == TT - 1 && full) {
                hfin[(size_t)b * HH + u] = hnew;
                cfin[(size_t)b * HH + u] = cnew;
            }
        }

        // ---- grid barrier (release/acquire, single poller) ----
        __syncthreads();
        if (tid == 0) bar_release_add(&g_arrive);

        // shadow: output stores (not consumed this pass)
#pragma unroll
        for (int pp = 0; pp < 2; pp++) {
            const int p = tid + pp * 256;
            const int b = p >> 3, ul = p & 7;
            outt[(size_t)b * HH + cta * 8 + ul] = hsave[pp];
        }

        if (tid == 0) {
            const int target = NCTA * (t + 1);
            while (bar_acquire_ld(&g_arrive) < target) __nanosleep(32);
        }
        __syncthreads();
    }
}

// ---------------------------------------------------------------------------
extern "C" void kernel_launch(void* const* d_in, const int* in_sizes, int n_in,
                              void* d_out, int out_size)
{
    const float* input_ = (const float*)d_in[0];
    const float* h0     = (const float*)d_in[1];
    const float* c0     = (const float*)d_in[2];
    const float* Wx     = (const float*)d_in[3];
    const float* Wh     = (const float*)d_in[4];
    const float* bx     = (const float*)d_in[5];
    const float* bh     = (const float*)d_in[6];
    float* out = (float*)d_out;
    (void)in_sizes; (void)n_in;

    cudaFuncSetAttribute(lstm_rec, cudaFuncAttributeMaxDynamicSharedMemorySize, SM_TOTAL);

    reset_bar<<<1, 1>>>();
    pack_whp<<<(G4 * HH) / 256, 256>>>(Wh);
    pack_wx<<<(G4 * HH) / 256, 256>>>(Wx);
    pack_x<<<(int)(((size_t)TT * BB * HH) / 256), 256>>>(input_);
    pack_h0<<<(BB * HH) / 256, 256>>>(h0);

    dim3 ggrid(G4 / 128, (TT * BB) / 128);
    gx_mma_kernel<<<ggrid, 256>>>(bx, bh);

    long long need = (long long)TT * BB * HH + 2LL * BB * HH;
    int full = (out_size >= need) ? 1 : 0;
    float* hfin = out + (size_t)TT * BB * HH;
    float* cfin = hfin + (size_t)BB * HH;

    lstm_rec<<<NCTA, 256, SM_TOTAL>>>(c0, out, hfin, cfin, full);
}